// round 8
// baseline (speedup 1.0000x reference)
#include <cuda_runtime.h>
#include <cuda_fp16.h>
#include <cstdint>

// LSTM cell: gates = [x|h] @ [Wx;Wh] + bx + bh, fused epilogue.
// B=16384, IN=H=512, K=1024, N=4H=2048.
// Round 8: occupancy 2 CTAs/SM. CTA tile 128x128, warp tile 64x32,
// gate-interleave granularity 8 (warp-local epilogue), <=128 regs,
// 111KB smem/CTA. fp16 mma m16n8k16 + ldmatrix, BK=64, 3-stage cp.async.

static constexpr int Bsz  = 16384;
static constexpr int INF  = 512;
static constexpr int Hd   = 512;
static constexpr int FH   = 2048;
static constexpr int Ktot = 1024;

#define BM 128
#define BN 128
#define BK 64
#define NSTAGE 3
#define NITER (Ktot / BK)              // 16
#define ROWSTR 72                      // halves per SMEM row (144 B)
#define A_STG_B (BM * ROWSTR * 2)      // 18432 B
#define B_STG_B (BN * ROWSTR * 2)      // 18432 B
#define STG_B   (A_STG_B + B_STG_B)    // 36864 B
#define SMEM_BYTES (512 + NSTAGE * STG_B)   // 111104

// prepass grid split
#define PREP_A_BLKS 4096
#define PREP_W_BLKS (32 * 64)
#define PREP_BLKS   (PREP_A_BLKS + PREP_W_BLKS)

__device__ __half g_A16[(size_t)Bsz * Ktot];   // 32 MB  [b][k]  (x | h)
__device__ __half g_Bt16[(size_t)FH * Ktot];   // 4 MB   [n'][k] gate-interleaved(8)

// ---------------- helpers ----------------
__device__ __forceinline__ uint32_t cvta_s(const void* p) {
    return (uint32_t)__cvta_generic_to_shared(p);
}
__device__ __forceinline__ void cpa16(uint32_t s, const void* g) {
    asm volatile("cp.async.cg.shared.global [%0], [%1], 16;"
                 :: "r"(s), "l"(g) : "memory");
}
__device__ __forceinline__ void ldm4(uint32_t* r, uint32_t a) {
    asm volatile("ldmatrix.sync.aligned.m8n8.x4.shared.b16 {%0,%1,%2,%3}, [%4];"
                 : "=r"(r[0]), "=r"(r[1]), "=r"(r[2]), "=r"(r[3]) : "r"(a));
}
__device__ __forceinline__ void mma16(float* d, const uint32_t* a, const uint32_t* b) {
    asm volatile(
        "mma.sync.aligned.m16n8k16.row.col.f32.f16.f16.f32 "
        "{%0,%1,%2,%3}, {%4,%5,%6,%7}, {%8,%9}, {%0,%1,%2,%3};"
        : "+f"(d[0]), "+f"(d[1]), "+f"(d[2]), "+f"(d[3])
        : "r"(a[0]), "r"(a[1]), "r"(a[2]), "r"(a[3]), "r"(b[0]), "r"(b[1]));
}
__device__ __forceinline__ float rcp_(float a) {
    float r; asm("rcp.approx.f32 %0, %1;" : "=f"(r) : "f"(a)); return r;
}
__device__ __forceinline__ float sigm_(float v) { return rcp_(1.0f + __expf(-v)); }
__device__ __forceinline__ float tanh_(float v) {
    return 2.0f * rcp_(1.0f + __expf(-2.0f * v)) - 1.0f;
}
__device__ __forceinline__ uint2 pack4h(float a, float b, float cc, float d) {
    union { __half2 h2[2]; uint2 u; } u;
    u.h2[0] = __floats2half2_rn(a, b);
    u.h2[1] = __floats2half2_rn(cc, d);
    return u.u;
}

// ---------------- merged prepass ----------------
// blocks [0, PREP_A_BLKS): convert x|h -> g_A16 (MLP=4)
// rest: 32x32 W transpose tiles -> g_Bt16, interleave granularity 8:
//   n' = (j>>3)*32 + gate*8 + (j&7)
__global__ void prep_all(const float* __restrict__ x, const float* __restrict__ h,
                         const float* __restrict__ Wx, const float* __restrict__ Wh)
{
    if (blockIdx.x < PREP_A_BLKS) {
        const size_t t = (size_t)blockIdx.x * 256 + threadIdx.x;
        const size_t NQ = (size_t)Bsz * INF / 4;
        const size_t S  = NQ / 2;
        float4 vx0 = *reinterpret_cast<const float4*>(x + (t)     * 4);
        float4 vx1 = *reinterpret_cast<const float4*>(x + (t + S) * 4);
        float4 vh0 = *reinterpret_cast<const float4*>(h + (t)     * 4);
        float4 vh1 = *reinterpret_cast<const float4*>(h + (t + S) * 4);
        {   size_t b = t >> 7, c4 = (t & 127) * 4;
            *reinterpret_cast<uint2*>(g_A16 + b * Ktot + c4) =
                pack4h(vx0.x, vx0.y, vx0.z, vx0.w); }
        {   size_t q = t + S; size_t b = q >> 7, c4 = (q & 127) * 4;
            *reinterpret_cast<uint2*>(g_A16 + b * Ktot + c4) =
                pack4h(vx1.x, vx1.y, vx1.z, vx1.w); }
        {   size_t b = t >> 7, c4 = (t & 127) * 4;
            *reinterpret_cast<uint2*>(g_A16 + b * Ktot + 512 + c4) =
                pack4h(vh0.x, vh0.y, vh0.z, vh0.w); }
        {   size_t q = t + S; size_t b = q >> 7, c4 = (q & 127) * 4;
            *reinterpret_cast<uint2*>(g_A16 + b * Ktot + 512 + c4) =
                pack4h(vh1.x, vh1.y, vh1.z, vh1.w); }
        return;
    }

    __shared__ float t[32][33];
    const int wb = blockIdx.x - PREP_A_BLKS;
    const int k0 = (wb & 31) * 32;
    const int n0 = (wb >> 5) * 32;
    const float* W = (k0 < INF) ? (Wx + (size_t)k0 * FH)
                                : (Wh + (size_t)(k0 - INF) * FH);
    const int tx = threadIdx.x & 31, ty = threadIdx.x >> 5;
    #pragma unroll
    for (int i = 0; i < 4; ++i) {
        int kk = ty + i * 8;
        t[kk][tx] = W[(size_t)kk * FH + n0 + tx];
    }
    __syncthreads();
    const int gate = n0 >> 9;
    const int j0   = n0 & 511;
    #pragma unroll
    for (int i = 0; i < 4; ++i) {
        int nn = ty + i * 8;
        int j  = j0 + nn;
        int np = ((j >> 3) << 5) + gate * 8 + (j & 7);
        g_Bt16[(size_t)np * Ktot + k0 + tx] = __float2half_rn(t[tx][nn]);
    }
}

// ---------------- main GEMM + LSTM epilogue ----------------
__global__ __launch_bounds__(256, 2)
void lstm_mma(const float* __restrict__ c,
              const float* __restrict__ bx, const float* __restrict__ bh,
              float* __restrict__ out)
{
    extern __shared__ char smraw[];
    float* biasS = reinterpret_cast<float*>(smraw);        // 128 floats
    char*  stg0  = smraw + 512;

    const int tid  = threadIdx.x;
    const int lane = tid & 31;
    const int wid  = tid >> 5;
    const int wm   = wid >> 2;              // 0..1  (64-row M half)
    const int wn   = wid & 3;               // 0..3  (32-col N quarter)
    const int m0   = blockIdx.y * BM;
    const int n0   = blockIdx.x * BN;
    const int jb   = blockIdx.x * 32;       // 32 hidden cols per CTA

    if (tid < 128) {   // bias = bx + bh, gate-major [gate][32 j]
        int g = tid >> 5, jj = tid & 31;
        int colg = g * 512 + jb + jj;
        biasS[tid] = bx[colg] + bh[colg];
    }

    float acc[4][4][4];                     // [mf][gate(n8)][frag]
    #pragma unroll
    for (int a = 0; a < 4; ++a)
        #pragma unroll
        for (int b = 0; b < 4; ++b)
            #pragma unroll
            for (int d = 0; d < 4; ++d) acc[a][b][d] = 0.0f;

    // ldmatrix per-lane geometry
    const int grp = lane >> 3, gi = lane & 7;
    const int a_row  = wm * 64 + (grp & 1) * 8 + gi;
    const int a_kofs = (grp >> 1) * 8;
    const uint32_t a_base = (uint32_t)(a_row * ROWSTR + a_kofs) * 2;
    const int b_row  = wn * 32 + (grp >> 1) * 8 + gi;
    const int b_kofs = (grp & 1) * 8;
    const uint32_t b_base = (uint32_t)(b_row * ROWSTR + b_kofs) * 2;

    // cp.async: A 4 chunks/thread, B 4 chunks/thread (16B each)
    auto load_stage = [&](int s, int kc) {
        const int k0 = kc * BK;
        char* As = stg0 + s * STG_B;
        char* Bs = As + A_STG_B;
        const __half* Ap = g_A16 + (size_t)m0 * Ktot + k0;
        #pragma unroll
        for (int p = 0; p < 4; ++p) {
            int q = tid + 256 * p, row = q >> 3, c8 = (q & 7) * 8;
            cpa16(cvta_s(As + (row * ROWSTR + c8) * 2),
                  Ap + (size_t)row * Ktot + c8);
        }
        const __half* Bp = g_Bt16 + (size_t)n0 * Ktot + k0;
        #pragma unroll
        for (int p = 0; p < 4; ++p) {
            int q = tid + 256 * p, row = q >> 3, c8 = (q & 7) * 8;
            cpa16(cvta_s(Bs + (row * ROWSTR + c8) * 2),
                  Bp + (size_t)row * Ktot + c8);
        }
        asm volatile("cp.async.commit_group;" ::: "memory");
    };

    load_stage(0, 0);
    load_stage(1, 1);

    for (int it = 0; it < NITER; ++it) {
        asm volatile("cp.async.wait_group 1;" ::: "memory");
        __syncthreads();   // publishes stage it AND guards stage being reloaded
        if (it + 2 < NITER) load_stage((it + 2) % NSTAGE, it + 2);
        else asm volatile("cp.async.commit_group;" ::: "memory");

        const uint32_t sA = cvta_s(stg0 + (it % NSTAGE) * STG_B);
        const uint32_t sB = sA + A_STG_B;

        #pragma unroll
        for (int ks = 0; ks < 4; ++ks) {             // four k16 steps per stage
            uint32_t afr[4][4], bfr[2][4];
            #pragma unroll
            for (int mf = 0; mf < 4; ++mf)
                ldm4(afr[mf], sA + a_base + mf * (16 * ROWSTR * 2) + ks * 32);
            #pragma unroll
            for (int np = 0; np < 2; ++np)
                ldm4(bfr[np], sB + b_base + np * (16 * ROWSTR * 2) + ks * 32);
            #pragma unroll
            for (int mf = 0; mf < 4; ++mf)
                #pragma unroll
                for (int np = 0; np < 2; ++np) {
                    mma16(acc[mf][np * 2 + 0], afr[mf], &bfr[np][0]);
                    mma16(acc[mf][np * 2 + 1], afr[mf], &bfr[np][2]);
                }
        }
        // no bottom barrier: next iteration's top barrier provides the guard
    }

    // ---- fused LSTM epilogue ----
    // acc[mf][g][*]: gate g values for j = jb + wn*8 + 2*(lane&3) (+1),
    // rows m0 + wm*64 + mf*16 + lane>>2 (+8 for frag e=1).
    const size_t HC = (size_t)Bsz * Hd;
    const int jq = jb + wn * 8 + 2 * (lane & 3);     // this thread's j pair
    const int bq = wn * 8 + 2 * (lane & 3);          // j within CTA's 32
    #pragma unroll
    for (int mf = 0; mf < 4; ++mf) {
        #pragma unroll
        for (int e = 0; e < 2; ++e) {
            size_t row = (size_t)m0 + wm * 64 + mf * 16 + (lane >> 2) + e * 8;
            float2 cold = *reinterpret_cast<const float2*>(c + row * 512 + jq);
            float hv[2], cv[2];
            #pragma unroll
            for (int d = 0; d < 2; ++d) {
                float gi = acc[mf][0][e * 2 + d] + biasS[     bq + d];
                float gf = acc[mf][1][e * 2 + d] + biasS[32 + bq + d];
                float gg = acc[mf][2][e * 2 + d] + biasS[64 + bq + d];
                float go = acc[mf][3][e * 2 + d] + biasS[96 + bq + d];
                float i_ = sigm_(gi), f_ = sigm_(gf);
                float g_ = tanh_(gg), o_ = sigm_(go);
                float co = d ? cold.y : cold.x;
                float cn = f_ * co + i_ * g_;
                cv[d] = cn;
                hv[d] = o_ * tanh_(cn);
            }
            *reinterpret_cast<float2*>(out + row * 512 + jq) =
                make_float2(hv[0], hv[1]);
            *reinterpret_cast<float2*>(out + HC + row * 512 + jq) =
                make_float2(cv[0], cv[1]);
        }
    }
}

extern "C" void kernel_launch(void* const* d_in, const int* in_sizes, int n_in,
                              void* d_out, int out_size) {
    const float* x  = (const float*)d_in[0];
    const float* h  = (const float*)d_in[1];
    const float* c  = (const float*)d_in[2];
    const float* Wx = (const float*)d_in[3];
    const float* Wh = (const float*)d_in[4];
    const float* bx = (const float*)d_in[5];
    const float* bh = (const float*)d_in[6];
    float* out = (float*)d_out;

    static bool attr_set = false;
    if (!attr_set) {
        cudaFuncSetAttribute(lstm_mma,
                             cudaFuncAttributeMaxDynamicSharedMemorySize,
                             SMEM_BYTES);
        attr_set = true;
    }

    prep_all<<<PREP_BLKS, 256>>>(x, h, Wx, Wh);
    lstm_mma<<<dim3(FH / BN, Bsz / BM), 256, SMEM_BYTES>>>(c, bx, bh, out);
}

// round 9
// speedup vs baseline: 1.4224x; 1.4224x over previous
#include <cuda_runtime.h>
#include <cuda_fp16.h>
#include <cstdint>

// LSTM cell: gates = [x|h] @ [Wx;Wh] + bx + bh, fused epilogue.
// B=16384, IN=H=512, K=1024, N=4H=2048.
// Round 9: 2 CTAs/SM WITHOUT shrinking the 64x64 warp tile:
// 128-thread CTAs, CTA tile 128x128, 4 warps (wm x wn = 2 x 2),
// 110KB smem/CTA, regs capped by __launch_bounds__(128,2).
// fp16 mma m16n8k16 + ldmatrix, BK=64, 3-stage cp.async,
// gate-interleave granularity 16 (R7's verified epilogue).

static constexpr int Bsz  = 16384;
static constexpr int INF  = 512;
static constexpr int Hd   = 512;
static constexpr int FH   = 2048;
static constexpr int Ktot = 1024;

#define BM 128
#define BN 128
#define BK 64
#define NSTAGE 3
#define NITER (Ktot / BK)              // 16
#define ROWSTR 72                      // halves per SMEM row (144 B)
#define A_STG_B (BM * ROWSTR * 2)      // 18432 B
#define B_STG_B (BN * ROWSTR * 2)      // 18432 B
#define STG_B   (A_STG_B + B_STG_B)    // 36864 B
#define SMEM_BYTES (512 + NSTAGE * STG_B)   // 111104

// prepass grid split
#define PREP_A_BLKS 4096
#define PREP_W_BLKS (32 * 64)
#define PREP_BLKS   (PREP_A_BLKS + PREP_W_BLKS)

__device__ __half g_A16[(size_t)Bsz * Ktot];   // 32 MB  [b][k]  (x | h)
__device__ __half g_Bt16[(size_t)FH * Ktot];   // 4 MB   [n'][k] gate-interleaved(16)

// ---------------- helpers ----------------
__device__ __forceinline__ uint32_t cvta_s(const void* p) {
    return (uint32_t)__cvta_generic_to_shared(p);
}
__device__ __forceinline__ void cpa16(uint32_t s, const void* g) {
    asm volatile("cp.async.cg.shared.global [%0], [%1], 16;"
                 :: "r"(s), "l"(g) : "memory");
}
__device__ __forceinline__ void ldm4(uint32_t* r, uint32_t a) {
    asm volatile("ldmatrix.sync.aligned.m8n8.x4.shared.b16 {%0,%1,%2,%3}, [%4];"
                 : "=r"(r[0]), "=r"(r[1]), "=r"(r[2]), "=r"(r[3]) : "r"(a));
}
__device__ __forceinline__ void mma16(float* d, const uint32_t* a, const uint32_t* b) {
    asm volatile(
        "mma.sync.aligned.m16n8k16.row.col.f32.f16.f16.f32 "
        "{%0,%1,%2,%3}, {%4,%5,%6,%7}, {%8,%9}, {%0,%1,%2,%3};"
        : "+f"(d[0]), "+f"(d[1]), "+f"(d[2]), "+f"(d[3])
        : "r"(a[0]), "r"(a[1]), "r"(a[2]), "r"(a[3]), "r"(b[0]), "r"(b[1]));
}
__device__ __forceinline__ float rcp_(float a) {
    float r; asm("rcp.approx.f32 %0, %1;" : "=f"(r) : "f"(a)); return r;
}
__device__ __forceinline__ float sigm_(float v) { return rcp_(1.0f + __expf(-v)); }
__device__ __forceinline__ float tanh_(float v) {
    return 2.0f * rcp_(1.0f + __expf(-2.0f * v)) - 1.0f;
}
__device__ __forceinline__ uint2 pack4h(float a, float b, float cc, float d) {
    union { __half2 h2[2]; uint2 u; } u;
    u.h2[0] = __floats2half2_rn(a, b);
    u.h2[1] = __floats2half2_rn(cc, d);
    return u.u;
}

// ---------------- merged prepass ----------------
// blocks [0, PREP_A_BLKS): convert x|h -> g_A16 (MLP=4)
// rest: 32x32 W transpose tiles -> g_Bt16, interleave granularity 16:
//   n' = (j>>4)*64 + gate*16 + (j&15)
__global__ void prep_all(const float* __restrict__ x, const float* __restrict__ h,
                         const float* __restrict__ Wx, const float* __restrict__ Wh)
{
    if (blockIdx.x < PREP_A_BLKS) {
        const size_t t = (size_t)blockIdx.x * 256 + threadIdx.x;
        const size_t NQ = (size_t)Bsz * INF / 4;
        const size_t S  = NQ / 2;
        float4 vx0 = *reinterpret_cast<const float4*>(x + (t)     * 4);
        float4 vx1 = *reinterpret_cast<const float4*>(x + (t + S) * 4);
        float4 vh0 = *reinterpret_cast<const float4*>(h + (t)     * 4);
        float4 vh1 = *reinterpret_cast<const float4*>(h + (t + S) * 4);
        {   size_t b = t >> 7, c4 = (t & 127) * 4;
            *reinterpret_cast<uint2*>(g_A16 + b * Ktot + c4) =
                pack4h(vx0.x, vx0.y, vx0.z, vx0.w); }
        {   size_t q = t + S; size_t b = q >> 7, c4 = (q & 127) * 4;
            *reinterpret_cast<uint2*>(g_A16 + b * Ktot + c4) =
                pack4h(vx1.x, vx1.y, vx1.z, vx1.w); }
        {   size_t b = t >> 7, c4 = (t & 127) * 4;
            *reinterpret_cast<uint2*>(g_A16 + b * Ktot + 512 + c4) =
                pack4h(vh0.x, vh0.y, vh0.z, vh0.w); }
        {   size_t q = t + S; size_t b = q >> 7, c4 = (q & 127) * 4;
            *reinterpret_cast<uint2*>(g_A16 + b * Ktot + 512 + c4) =
                pack4h(vh1.x, vh1.y, vh1.z, vh1.w); }
        return;
    }

    __shared__ float t[32][33];
    const int wb = blockIdx.x - PREP_A_BLKS;
    const int k0 = (wb & 31) * 32;
    const int n0 = (wb >> 5) * 32;
    const float* W = (k0 < INF) ? (Wx + (size_t)k0 * FH)
                                : (Wh + (size_t)(k0 - INF) * FH);
    const int tx = threadIdx.x & 31, ty = threadIdx.x >> 5;
    #pragma unroll
    for (int i = 0; i < 4; ++i) {
        int kk = ty + i * 8;
        t[kk][tx] = W[(size_t)kk * FH + n0 + tx];
    }
    __syncthreads();
    const int gate = n0 >> 9;
    const int j0   = n0 & 511;
    #pragma unroll
    for (int i = 0; i < 4; ++i) {
        int nn = ty + i * 8;
        int j  = j0 + nn;
        int np = ((j >> 4) << 6) + gate * 16 + (j & 15);
        g_Bt16[(size_t)np * Ktot + k0 + tx] = __float2half_rn(t[tx][nn]);
    }
}

// ---------------- main GEMM + LSTM epilogue ----------------
__global__ __launch_bounds__(128, 2)
void lstm_mma(const float* __restrict__ c,
              const float* __restrict__ bx, const float* __restrict__ bh,
              float* __restrict__ out)
{
    extern __shared__ char smraw[];
    float* biasS = reinterpret_cast<float*>(smraw);        // 128 floats
    char*  stg0  = smraw + 512;

    const int tid  = threadIdx.x;
    const int lane = tid & 31;
    const int wid  = tid >> 5;              // 0..3
    const int wm   = wid >> 1;              // 0..1  (64-row M half)
    const int wn   = wid & 1;               // 0..1  (64-col N half)
    const int m0   = blockIdx.y * BM;
    const int n0   = blockIdx.x * BN;
    const int jb   = blockIdx.x * 32;       // 32 hidden cols per CTA

    {   // bias = bx + bh, gate-major [gate][32 j]
        int g = tid >> 5, jj = tid & 31;
        int colg = g * 512 + jb + jj;
        biasS[tid] = bx[colg] + bh[colg];
    }

    float acc[4][8][4];                     // [mf][gate*2+half][frag]
    #pragma unroll
    for (int a = 0; a < 4; ++a)
        #pragma unroll
        for (int b = 0; b < 8; ++b)
            #pragma unroll
            for (int d = 0; d < 4; ++d) acc[a][b][d] = 0.0f;

    // ldmatrix per-lane geometry
    const int grp = lane >> 3, gi = lane & 7;
    const int a_row  = wm * 64 + (grp & 1) * 8 + gi;
    const int a_kofs = (grp >> 1) * 8;
    const uint32_t a_base = (uint32_t)(a_row * ROWSTR + a_kofs) * 2;
    const int b_row  = wn * 64 + (grp >> 1) * 8 + gi;
    const int b_kofs = (grp & 1) * 8;
    const uint32_t b_base = (uint32_t)(b_row * ROWSTR + b_kofs) * 2;

    // cp.async: 128 threads, A 8 chunks/thread, B 8 chunks/thread (16B each)
    auto load_stage = [&](int s, int kc) {
        const int k0 = kc * BK;
        char* As = stg0 + s * STG_B;
        char* Bs = As + A_STG_B;
        const __half* Ap = g_A16 + (size_t)m0 * Ktot + k0;
        #pragma unroll
        for (int p = 0; p < 8; ++p) {
            int q = tid + 128 * p, row = q >> 3, c8 = (q & 7) * 8;
            cpa16(cvta_s(As + (row * ROWSTR + c8) * 2),
                  Ap + (size_t)row * Ktot + c8);
        }
        const __half* Bp = g_Bt16 + (size_t)n0 * Ktot + k0;
        #pragma unroll
        for (int p = 0; p < 8; ++p) {
            int q = tid + 128 * p, row = q >> 3, c8 = (q & 7) * 8;
            cpa16(cvta_s(Bs + (row * ROWSTR + c8) * 2),
                  Bp + (size_t)row * Ktot + c8);
        }
        asm volatile("cp.async.commit_group;" ::: "memory");
    };

    load_stage(0, 0);
    load_stage(1, 1);

    uint32_t afr[2][4][4], bfr[2][4][4];

    for (int it = 0; it < NITER; ++it) {
        asm volatile("cp.async.wait_group 1;" ::: "memory");
        __syncthreads();   // publishes stage it AND guards stage being reloaded
        if (it + 2 < NITER) load_stage((it + 2) % NSTAGE, it + 2);
        else asm volatile("cp.async.commit_group;" ::: "memory");

        const uint32_t sA = cvta_s(stg0 + (it % NSTAGE) * STG_B);
        const uint32_t sB = sA + A_STG_B;

        // preload fragments for ks=0
        #pragma unroll
        for (int mf = 0; mf < 4; ++mf)
            ldm4(afr[0][mf], sA + a_base + mf * (16 * ROWSTR * 2));
        #pragma unroll
        for (int np = 0; np < 4; ++np)
            ldm4(bfr[0][np], sB + b_base + np * (16 * ROWSTR * 2));

        #pragma unroll
        for (int ks = 0; ks < 4; ++ks) {             // four k16 steps per stage
            const int cur = ks & 1;
            if (ks < 3) {                            // prefetch next k16 frags
                const int nxt = cur ^ 1;
                #pragma unroll
                for (int mf = 0; mf < 4; ++mf)
                    ldm4(afr[nxt][mf],
                         sA + a_base + mf * (16 * ROWSTR * 2) + (ks + 1) * 32);
                #pragma unroll
                for (int np = 0; np < 4; ++np)
                    ldm4(bfr[nxt][np],
                         sB + b_base + np * (16 * ROWSTR * 2) + (ks + 1) * 32);
            }
            #pragma unroll
            for (int mf = 0; mf < 4; ++mf)
                #pragma unroll
                for (int np = 0; np < 4; ++np) {
                    mma16(acc[mf][np * 2 + 0], afr[cur][mf], &bfr[cur][np][0]);
                    mma16(acc[mf][np * 2 + 1], afr[cur][mf], &bfr[cur][np][2]);
                }
        }
        // no bottom barrier: next iteration's top barrier provides the guard
    }

    // ---- fused LSTM epilogue (thread-local: all 4 gates per j) ----
    const size_t HC = (size_t)Bsz * Hd;
    #pragma unroll
    for (int mf = 0; mf < 4; ++mf) {
        #pragma unroll
        for (int e = 0; e < 2; ++e) {
            size_t row = (size_t)m0 + wm * 64 + mf * 16 + (lane >> 2) + e * 8;
            #pragma unroll
            for (int half = 0; half < 2; ++half) {
                int q  = 2 * (lane & 3) + half * 8;   // j within warp's 16
                int bq = wn * 16 + q;                 // j within CTA's 32
                int j  = jb + bq;
                float2 cold = *reinterpret_cast<const float2*>(c + row * 512 + j);
                float hv[2], cv[2];
                #pragma unroll
                for (int d = 0; d < 2; ++d) {
                    float gi = acc[mf][0 + half][e * 2 + d] + biasS[     bq + d];
                    float gf = acc[mf][2 + half][e * 2 + d] + biasS[32 + bq + d];
                    float gg = acc[mf][4 + half][e * 2 + d] + biasS[64 + bq + d];
                    float go = acc[mf][6 + half][e * 2 + d] + biasS[96 + bq + d];
                    float i_ = sigm_(gi), f_ = sigm_(gf);
                    float g_ = tanh_(gg), o_ = sigm_(go);
                    float co = d ? cold.y : cold.x;
                    float cn = f_ * co + i_ * g_;
                    cv[d] = cn;
                    hv[d] = o_ * tanh_(cn);
                }
                *reinterpret_cast<float2*>(out + row * 512 + j) =
                    make_float2(hv[0], hv[1]);
                *reinterpret_cast<float2*>(out + HC + row * 512 + j) =
                    make_float2(cv[0], cv[1]);
            }
        }
    }
}

extern "C" void kernel_launch(void* const* d_in, const int* in_sizes, int n_in,
                              void* d_out, int out_size) {
    const float* x  = (const float*)d_in[0];
    const float* h  = (const float*)d_in[1];
    const float* c  = (const float*)d_in[2];
    const float* Wx = (const float*)d_in[3];
    const float* Wh = (const float*)d_in[4];
    const float* bx = (const float*)d_in[5];
    const float* bh = (const float*)d_in[6];
    float* out = (float*)d_out;

    static bool attr_set = false;
    if (!attr_set) {
        cudaFuncSetAttribute(lstm_mma,
                             cudaFuncAttributeMaxDynamicSharedMemorySize,
                             SMEM_BYTES);
        attr_set = true;
    }

    prep_all<<<PREP_BLKS, 256>>>(x, h, Wx, Wh);
    lstm_mma<<<dim3(FH / BN, Bsz / BM), 128, SMEM_BYTES>>>(c, bx, bh, out);
}

// round 10
// speedup vs baseline: 1.5484x; 1.0885x over previous
#include <cuda_runtime.h>
#include <cuda_fp16.h>
#include <cstdint>

// LSTM cell: gates = [x|h] @ [Wx;Wh] + bx + bh, fused epilogue.
// B=16384, IN=H=512, K=1024, N=4H=2048.
// Round 10: mbarrier producer/consumer pipeline -- NO CTA-wide barriers in
// the mainloop. full[s] armed by cp.async.mbarrier.arrive.noinc (count=128),
// empty[s] armed by per-thread arrives after a stage's last ldmatrix.
// Tiles/fragments/epilogue identical to R9 (128-thr CTA, 128x128 tile,
// 64x64 warp tile, BK=64, 3 stages, gate-interleave 16).

static constexpr int Bsz  = 16384;
static constexpr int INF  = 512;
static constexpr int Hd   = 512;
static constexpr int FH   = 2048;
static constexpr int Ktot = 1024;

#define BM 128
#define BN 128
#define BK 64
#define NSTAGE 3
#define NITER (Ktot / BK)              // 16
#define ROWSTR 72                      // halves per SMEM row (144 B)
#define A_STG_B (BM * ROWSTR * 2)      // 18432 B
#define B_STG_B (BN * ROWSTR * 2)      // 18432 B
#define STG_B   (A_STG_B + B_STG_B)    // 36864 B
#define SMEM_BYTES (1024 + NSTAGE * STG_B)   // 111616

// prepass grid split
#define PREP_A_BLKS 4096
#define PREP_W_BLKS (32 * 64)
#define PREP_BLKS   (PREP_A_BLKS + PREP_W_BLKS)

__device__ __half g_A16[(size_t)Bsz * Ktot];   // 32 MB  [b][k]  (x | h)
__device__ __half g_Bt16[(size_t)FH * Ktot];   // 4 MB   [n'][k] gate-interleaved(16)

// ---------------- helpers ----------------
__device__ __forceinline__ uint32_t cvta_s(const void* p) {
    return (uint32_t)__cvta_generic_to_shared(p);
}
__device__ __forceinline__ void cpa16(uint32_t s, const void* g) {
    asm volatile("cp.async.cg.shared.global [%0], [%1], 16;"
                 :: "r"(s), "l"(g) : "memory");
}
__device__ __forceinline__ void mbar_init(uint32_t a, uint32_t cnt) {
    asm volatile("mbarrier.init.shared.b64 [%0], %1;" :: "r"(a), "r"(cnt) : "memory");
}
__device__ __forceinline__ void mbar_arrive(uint32_t a) {
    asm volatile("mbarrier.arrive.shared.b64 _, [%0];" :: "r"(a) : "memory");
}
__device__ __forceinline__ void cpa_mbar_arrive(uint32_t a) {
    asm volatile("cp.async.mbarrier.arrive.noinc.shared.b64 [%0];"
                 :: "r"(a) : "memory");
}
__device__ __forceinline__ void mbar_wait(uint32_t a, uint32_t ph) {
    uint32_t done = 0;
    while (!done) {
        asm volatile(
            "{\n\t.reg .pred p;\n\t"
            "mbarrier.try_wait.parity.acquire.cta.shared::cta.b64 p, [%1], %2, 0x989680;\n\t"
            "selp.b32 %0, 1, 0, p;\n\t}"
            : "=r"(done) : "r"(a), "r"(ph) : "memory");
    }
}
__device__ __forceinline__ void ldm4(uint32_t* r, uint32_t a) {
    asm volatile("ldmatrix.sync.aligned.m8n8.x4.shared.b16 {%0,%1,%2,%3}, [%4];"
                 : "=r"(r[0]), "=r"(r[1]), "=r"(r[2]), "=r"(r[3]) : "r"(a));
}
__device__ __forceinline__ void mma16(float* d, const uint32_t* a, const uint32_t* b) {
    asm volatile(
        "mma.sync.aligned.m16n8k16.row.col.f32.f16.f16.f32 "
        "{%0,%1,%2,%3}, {%4,%5,%6,%7}, {%8,%9}, {%0,%1,%2,%3};"
        : "+f"(d[0]), "+f"(d[1]), "+f"(d[2]), "+f"(d[3])
        : "r"(a[0]), "r"(a[1]), "r"(a[2]), "r"(a[3]), "r"(b[0]), "r"(b[1]));
}
__device__ __forceinline__ float rcp_(float a) {
    float r; asm("rcp.approx.f32 %0, %1;" : "=f"(r) : "f"(a)); return r;
}
__device__ __forceinline__ float sigm_(float v) { return rcp_(1.0f + __expf(-v)); }
__device__ __forceinline__ float tanh_(float v) {
    return 2.0f * rcp_(1.0f + __expf(-2.0f * v)) - 1.0f;
}
__device__ __forceinline__ uint2 pack4h(float a, float b, float cc, float d) {
    union { __half2 h2[2]; uint2 u; } u;
    u.h2[0] = __floats2half2_rn(a, b);
    u.h2[1] = __floats2half2_rn(cc, d);
    return u.u;
}

// ---------------- merged prepass (unchanged, verified) ----------------
__global__ void prep_all(const float* __restrict__ x, const float* __restrict__ h,
                         const float* __restrict__ Wx, const float* __restrict__ Wh)
{
    if (blockIdx.x < PREP_A_BLKS) {
        const size_t t = (size_t)blockIdx.x * 256 + threadIdx.x;
        const size_t NQ = (size_t)Bsz * INF / 4;
        const size_t S  = NQ / 2;
        float4 vx0 = *reinterpret_cast<const float4*>(x + (t)     * 4);
        float4 vx1 = *reinterpret_cast<const float4*>(x + (t + S) * 4);
        float4 vh0 = *reinterpret_cast<const float4*>(h + (t)     * 4);
        float4 vh1 = *reinterpret_cast<const float4*>(h + (t + S) * 4);
        {   size_t b = t >> 7, c4 = (t & 127) * 4;
            *reinterpret_cast<uint2*>(g_A16 + b * Ktot + c4) =
                pack4h(vx0.x, vx0.y, vx0.z, vx0.w); }
        {   size_t q = t + S; size_t b = q >> 7, c4 = (q & 127) * 4;
            *reinterpret_cast<uint2*>(g_A16 + b * Ktot + c4) =
                pack4h(vx1.x, vx1.y, vx1.z, vx1.w); }
        {   size_t b = t >> 7, c4 = (t & 127) * 4;
            *reinterpret_cast<uint2*>(g_A16 + b * Ktot + 512 + c4) =
                pack4h(vh0.x, vh0.y, vh0.z, vh0.w); }
        {   size_t q = t + S; size_t b = q >> 7, c4 = (q & 127) * 4;
            *reinterpret_cast<uint2*>(g_A16 + b * Ktot + 512 + c4) =
                pack4h(vh1.x, vh1.y, vh1.z, vh1.w); }
        return;
    }

    __shared__ float t[32][33];
    const int wb = blockIdx.x - PREP_A_BLKS;
    const int k0 = (wb & 31) * 32;
    const int n0 = (wb >> 5) * 32;
    const float* W = (k0 < INF) ? (Wx + (size_t)k0 * FH)
                                : (Wh + (size_t)(k0 - INF) * FH);
    const int tx = threadIdx.x & 31, ty = threadIdx.x >> 5;
    #pragma unroll
    for (int i = 0; i < 4; ++i) {
        int kk = ty + i * 8;
        t[kk][tx] = W[(size_t)kk * FH + n0 + tx];
    }
    __syncthreads();
    const int gate = n0 >> 9;
    const int j0   = n0 & 511;
    #pragma unroll
    for (int i = 0; i < 4; ++i) {
        int nn = ty + i * 8;
        int j  = j0 + nn;
        int np = ((j >> 4) << 6) + gate * 16 + (j & 15);
        g_Bt16[(size_t)np * Ktot + k0 + tx] = __float2half_rn(t[tx][nn]);
    }
}

// ---------------- main GEMM + LSTM epilogue ----------------
__global__ __launch_bounds__(128, 2)
void lstm_mma(const float* __restrict__ c,
              const float* __restrict__ bx, const float* __restrict__ bh,
              float* __restrict__ out)
{
    extern __shared__ char smraw[];
    float* biasS = reinterpret_cast<float*>(smraw);        // 128 floats @0
    char*  stg0  = smraw + 1024;

    const int tid  = threadIdx.x;
    const int lane = tid & 31;
    const int wid  = tid >> 5;              // 0..3
    const int wm   = wid >> 1;              // 0..1
    const int wn   = wid & 1;               // 0..1
    const int m0   = blockIdx.y * BM;
    const int n0   = blockIdx.x * BN;
    const int jb   = blockIdx.x * 32;

    const uint32_t sbase = cvta_s(smraw);
    const uint32_t FULLB = sbase + 512;               // full[0..2], 8 B each
    const uint32_t EMPTB = sbase + 512 + 24;          // empty[0..2]

    if (tid == 0) {
        #pragma unroll
        for (int s = 0; s < NSTAGE; ++s) {
            mbar_init(FULLB + s * 8, 128);
            mbar_init(EMPTB + s * 8, 128);
        }
    }
    {   // bias = bx + bh, gate-major [gate][32 j]
        int g = tid >> 5, jj = tid & 31;
        int colg = g * 512 + jb + jj;
        biasS[tid] = bx[colg] + bh[colg];
    }
    __syncthreads();    // publishes mbarrier init + bias (only CTA barrier)

    float acc[4][8][4];
    #pragma unroll
    for (int a = 0; a < 4; ++a)
        #pragma unroll
        for (int b = 0; b < 8; ++b)
            #pragma unroll
            for (int d = 0; d < 4; ++d) acc[a][b][d] = 0.0f;

    // ldmatrix per-lane geometry
    const int grp = lane >> 3, gi = lane & 7;
    const int a_row  = wm * 64 + (grp & 1) * 8 + gi;
    const int a_kofs = (grp >> 1) * 8;
    const uint32_t a_base = (uint32_t)(a_row * ROWSTR + a_kofs) * 2;
    const int b_row  = wn * 64 + (grp >> 1) * 8 + gi;
    const int b_kofs = (grp & 1) * 8;
    const uint32_t b_base = (uint32_t)(b_row * ROWSTR + b_kofs) * 2;

    // cp.async: 128 threads, A 8 chunks/thread, B 8 chunks/thread (16B each),
    // then arm full[s] via arrive-on-completion.
    auto load_stage = [&](int s, int kc) {
        const int k0 = kc * BK;
        char* As = stg0 + s * STG_B;
        char* Bs = As + A_STG_B;
        const __half* Ap = g_A16 + (size_t)m0 * Ktot + k0;
        #pragma unroll
        for (int p = 0; p < 8; ++p) {
            int q = tid + 128 * p, row = q >> 3, c8 = (q & 7) * 8;
            cpa16(cvta_s(As + (row * ROWSTR + c8) * 2),
                  Ap + (size_t)row * Ktot + c8);
        }
        const __half* Bp = g_Bt16 + (size_t)n0 * Ktot + k0;
        #pragma unroll
        for (int p = 0; p < 8; ++p) {
            int q = tid + 128 * p, row = q >> 3, c8 = (q & 7) * 8;
            cpa16(cvta_s(Bs + (row * ROWSTR + c8) * 2),
                  Bp + (size_t)row * Ktot + c8);
        }
        cpa_mbar_arrive(FULLB + s * 8);
    };

    load_stage(0, 0);
    load_stage(1, 1);

    uint32_t afr[2][4][4], bfr[2][4][4];
    int fph0 = 0, fph1 = 0, fph2 = 0;     // full parity per stage
    int eph0 = 0, eph1 = 0, eph2 = 0;     // empty parity per stage

    for (int it = 0; it < NITER; ++it) {
        const int s = it % NSTAGE;

        // producer: refill stage (it+2)%3 once its previous consumers drained
        if (it + 2 < NITER) {
            const int s2 = (it + 2) % NSTAGE;
            if (it > 0) {      // stage s2 was consumed at iteration it-1
                int ph = (s2 == 0) ? eph0 : (s2 == 1) ? eph1 : eph2;
                mbar_wait(EMPTB + s2 * 8, ph);
                if (s2 == 0) eph0 ^= 1; else if (s2 == 1) eph1 ^= 1; else eph2 ^= 1;
            }
            load_stage(s2, it + 2);
        }

        // consumer: wait for stage s data
        {
            int ph = (s == 0) ? fph0 : (s == 1) ? fph1 : fph2;
            mbar_wait(FULLB + s * 8, ph);
            if (s == 0) fph0 ^= 1; else if (s == 1) fph1 ^= 1; else fph2 ^= 1;
        }

        const uint32_t sA = cvta_s(stg0 + s * STG_B);
        const uint32_t sB = sA + A_STG_B;

        // preload fragments for ks=0
        #pragma unroll
        for (int mf = 0; mf < 4; ++mf)
            ldm4(afr[0][mf], sA + a_base + mf * (16 * ROWSTR * 2));
        #pragma unroll
        for (int np = 0; np < 4; ++np)
            ldm4(bfr[0][np], sB + b_base + np * (16 * ROWSTR * 2));

        #pragma unroll
        for (int ks = 0; ks < 4; ++ks) {
            const int cur = ks & 1;
            if (ks < 3) {                            // prefetch next k16 frags
                const int nxt = cur ^ 1;
                #pragma unroll
                for (int mf = 0; mf < 4; ++mf)
                    ldm4(afr[nxt][mf],
                         sA + a_base + mf * (16 * ROWSTR * 2) + (ks + 1) * 32);
                #pragma unroll
                for (int np = 0; np < 4; ++np)
                    ldm4(bfr[nxt][np],
                         sB + b_base + np * (16 * ROWSTR * 2) + (ks + 1) * 32);
                if (ks == 2)                 // last smem read of stage s issued
                    mbar_arrive(EMPTB + s * 8);
            }
            #pragma unroll
            for (int mf = 0; mf < 4; ++mf)
                #pragma unroll
                for (int np = 0; np < 4; ++np) {
                    mma16(acc[mf][np * 2 + 0], afr[cur][mf], &bfr[cur][np][0]);
                    mma16(acc[mf][np * 2 + 1], afr[cur][mf], &bfr[cur][np][2]);
                }
        }
    }

    // ---- fused LSTM epilogue (thread-local: all 4 gates per j) ----
    const size_t HC = (size_t)Bsz * Hd;
    #pragma unroll
    for (int mf = 0; mf < 4; ++mf) {
        #pragma unroll
        for (int e = 0; e < 2; ++e) {
            size_t row = (size_t)m0 + wm * 64 + mf * 16 + (lane >> 2) + e * 8;
            #pragma unroll
            for (int half = 0; half < 2; ++half) {
                int q  = 2 * (lane & 3) + half * 8;
                int bq = wn * 16 + q;
                int j  = jb + bq;
                float2 cold = *reinterpret_cast<const float2*>(c + row * 512 + j);
                float hv[2], cv[2];
                #pragma unroll
                for (int d = 0; d < 2; ++d) {
                    float gi = acc[mf][0 + half][e * 2 + d] + biasS[     bq + d];
                    float gf = acc[mf][2 + half][e * 2 + d] + biasS[32 + bq + d];
                    float gg = acc[mf][4 + half][e * 2 + d] + biasS[64 + bq + d];
                    float go = acc[mf][6 + half][e * 2 + d] + biasS[96 + bq + d];
                    float i_ = sigm_(gi), f_ = sigm_(gf);
                    float g_ = tanh_(gg), o_ = sigm_(go);
                    float co = d ? cold.y : cold.x;
                    float cn = f_ * co + i_ * g_;
                    cv[d] = cn;
                    hv[d] = o_ * tanh_(cn);
                }
                *reinterpret_cast<float2*>(out + row * 512 + j) =
                    make_float2(hv[0], hv[1]);
                *reinterpret_cast<float2*>(out + HC + row * 512 + j) =
                    make_float2(cv[0], cv[1]);
            }
        }
    }
}

extern "C" void kernel_launch(void* const* d_in, const int* in_sizes, int n_in,
                              void* d_out, int out_size) {
    const float* x  = (const float*)d_in[0];
    const float* h  = (const float*)d_in[1];
    const float* c  = (const float*)d_in[2];
    const float* Wx = (const float*)d_in[3];
    const float* Wh = (const float*)d_in[4];
    const float* bx = (const float*)d_in[5];
    const float* bh = (const float*)d_in[6];
    float* out = (float*)d_out;

    static bool attr_set = false;
    if (!attr_set) {
        cudaFuncSetAttribute(lstm_mma,
                             cudaFuncAttributeMaxDynamicSharedMemorySize,
                             SMEM_BYTES);
        attr_set = true;
    }

    prep_all<<<PREP_BLKS, 256>>>(x, h, Wx, Wh);
    lstm_mma<<<dim3(FH / BN, Bsz / BM), 128, SMEM_BYTES>>>(c, bx, bh, out);
}

// round 11
// speedup vs baseline: 1.6718x; 1.0797x over previous
#include <cuda_runtime.h>
#include <cuda_fp16.h>
#include <cstdint>

// LSTM cell: gates = [x|h] @ [Wx;Wh] + bx + bh, fused epilogue.
// B=16384, IN=H=512, K=1024, N=4H=2048.
// Round 11: cross-stage fragment prefetch. During ks=3 of stage s the warp
// waits full[s+1] (posted ~2 iters earlier; fast-path) and preloads stage
// s+1's ks=0 fragments, so the 64-step MMA stream never exposes ldmatrix
// latency. Otherwise identical to R10 (mbarrier pipeline, 128-thr CTAs,
// 2 CTAs/SM, 128x128 tile, 64x64 warp tile, BK=64, gate-interleave 16).

static constexpr int Bsz  = 16384;
static constexpr int INF  = 512;
static constexpr int Hd   = 512;
static constexpr int FH   = 2048;
static constexpr int Ktot = 1024;

#define BM 128
#define BN 128
#define BK 64
#define NSTAGE 3
#define NITER (Ktot / BK)              // 16
#define ROWSTR 72                      // halves per SMEM row (144 B)
#define A_STG_B (BM * ROWSTR * 2)      // 18432 B
#define B_STG_B (BN * ROWSTR * 2)      // 18432 B
#define STG_B   (A_STG_B + B_STG_B)    // 36864 B
#define SMEM_BYTES (1024 + NSTAGE * STG_B)   // 111616

#define PREP_A_BLKS 4096
#define PREP_W_BLKS (32 * 64)
#define PREP_BLKS   (PREP_A_BLKS + PREP_W_BLKS)

__device__ __half g_A16[(size_t)Bsz * Ktot];   // 32 MB  [b][k]  (x | h)
__device__ __half g_Bt16[(size_t)FH * Ktot];   // 4 MB   [n'][k] gate-interleaved(16)

// ---------------- helpers ----------------
__device__ __forceinline__ uint32_t cvta_s(const void* p) {
    return (uint32_t)__cvta_generic_to_shared(p);
}
__device__ __forceinline__ void cpa16(uint32_t s, const void* g) {
    asm volatile("cp.async.cg.shared.global [%0], [%1], 16;"
                 :: "r"(s), "l"(g) : "memory");
}
__device__ __forceinline__ void mbar_init(uint32_t a, uint32_t cnt) {
    asm volatile("mbarrier.init.shared.b64 [%0], %1;" :: "r"(a), "r"(cnt) : "memory");
}
__device__ __forceinline__ void mbar_arrive(uint32_t a) {
    asm volatile("mbarrier.arrive.shared.b64 _, [%0];" :: "r"(a) : "memory");
}
__device__ __forceinline__ void cpa_mbar_arrive(uint32_t a) {
    asm volatile("cp.async.mbarrier.arrive.noinc.shared.b64 [%0];"
                 :: "r"(a) : "memory");
}
__device__ __forceinline__ void mbar_wait(uint32_t a, uint32_t ph) {
    uint32_t done = 0;
    while (!done) {
        asm volatile(
            "{\n\t.reg .pred p;\n\t"
            "mbarrier.try_wait.parity.acquire.cta.shared::cta.b64 p, [%1], %2, 0x989680;\n\t"
            "selp.b32 %0, 1, 0, p;\n\t}"
            : "=r"(done) : "r"(a), "r"(ph) : "memory");
    }
}
__device__ __forceinline__ void ldm4(uint32_t* r, uint32_t a) {
    asm volatile("ldmatrix.sync.aligned.m8n8.x4.shared.b16 {%0,%1,%2,%3}, [%4];"
                 : "=r"(r[0]), "=r"(r[1]), "=r"(r[2]), "=r"(r[3]) : "r"(a));
}
__device__ __forceinline__ void mma16(float* d, const uint32_t* a, const uint32_t* b) {
    asm volatile(
        "mma.sync.aligned.m16n8k16.row.col.f32.f16.f16.f32 "
        "{%0,%1,%2,%3}, {%4,%5,%6,%7}, {%8,%9}, {%0,%1,%2,%3};"
        : "+f"(d[0]), "+f"(d[1]), "+f"(d[2]), "+f"(d[3])
        : "r"(a[0]), "r"(a[1]), "r"(a[2]), "r"(a[3]), "r"(b[0]), "r"(b[1]));
}
__device__ __forceinline__ float rcp_(float a) {
    float r; asm("rcp.approx.f32 %0, %1;" : "=f"(r) : "f"(a)); return r;
}
__device__ __forceinline__ float sigm_(float v) { return rcp_(1.0f + __expf(-v)); }
__device__ __forceinline__ float tanh_(float v) {
    return 2.0f * rcp_(1.0f + __expf(-2.0f * v)) - 1.0f;
}
__device__ __forceinline__ uint2 pack4h(float a, float b, float cc, float d) {
    union { __half2 h2[2]; uint2 u; } u;
    u.h2[0] = __floats2half2_rn(a, b);
    u.h2[1] = __floats2half2_rn(cc, d);
    return u.u;
}

// ---------------- merged prepass (unchanged, verified) ----------------
__global__ void prep_all(const float* __restrict__ x, const float* __restrict__ h,
                         const float* __restrict__ Wx, const float* __restrict__ Wh)
{
    if (blockIdx.x < PREP_A_BLKS) {
        const size_t t = (size_t)blockIdx.x * 256 + threadIdx.x;
        const size_t NQ = (size_t)Bsz * INF / 4;
        const size_t S  = NQ / 2;
        float4 vx0 = *reinterpret_cast<const float4*>(x + (t)     * 4);
        float4 vx1 = *reinterpret_cast<const float4*>(x + (t + S) * 4);
        float4 vh0 = *reinterpret_cast<const float4*>(h + (t)     * 4);
        float4 vh1 = *reinterpret_cast<const float4*>(h + (t + S) * 4);
        {   size_t b = t >> 7, c4 = (t & 127) * 4;
            *reinterpret_cast<uint2*>(g_A16 + b * Ktot + c4) =
                pack4h(vx0.x, vx0.y, vx0.z, vx0.w); }
        {   size_t q = t + S; size_t b = q >> 7, c4 = (q & 127) * 4;
            *reinterpret_cast<uint2*>(g_A16 + b * Ktot + c4) =
                pack4h(vx1.x, vx1.y, vx1.z, vx1.w); }
        {   size_t b = t >> 7, c4 = (t & 127) * 4;
            *reinterpret_cast<uint2*>(g_A16 + b * Ktot + 512 + c4) =
                pack4h(vh0.x, vh0.y, vh0.z, vh0.w); }
        {   size_t q = t + S; size_t b = q >> 7, c4 = (q & 127) * 4;
            *reinterpret_cast<uint2*>(g_A16 + b * Ktot + 512 + c4) =
                pack4h(vh1.x, vh1.y, vh1.z, vh1.w); }
        return;
    }

    __shared__ float t[32][33];
    const int wb = blockIdx.x - PREP_A_BLKS;
    const int k0 = (wb & 31) * 32;
    const int n0 = (wb >> 5) * 32;
    const float* W = (k0 < INF) ? (Wx + (size_t)k0 * FH)
                                : (Wh + (size_t)(k0 - INF) * FH);
    const int tx = threadIdx.x & 31, ty = threadIdx.x >> 5;
    #pragma unroll
    for (int i = 0; i < 4; ++i) {
        int kk = ty + i * 8;
        t[kk][tx] = W[(size_t)kk * FH + n0 + tx];
    }
    __syncthreads();
    const int gate = n0 >> 9;
    const int j0   = n0 & 511;
    #pragma unroll
    for (int i = 0; i < 4; ++i) {
        int nn = ty + i * 8;
        int j  = j0 + nn;
        int np = ((j >> 4) << 6) + gate * 16 + (j & 15);
        g_Bt16[(size_t)np * Ktot + k0 + tx] = __float2half_rn(t[tx][nn]);
    }
}

// ---------------- main GEMM + LSTM epilogue ----------------
__global__ __launch_bounds__(128, 2)
void lstm_mma(const float* __restrict__ c,
              const float* __restrict__ bx, const float* __restrict__ bh,
              float* __restrict__ out)
{
    extern __shared__ char smraw[];
    float* biasS = reinterpret_cast<float*>(smraw);        // 128 floats @0
    char*  stg0  = smraw + 1024;

    const int tid  = threadIdx.x;
    const int lane = tid & 31;
    const int wid  = tid >> 5;
    const int wm   = wid >> 1;
    const int wn   = wid & 1;
    const int m0   = blockIdx.y * BM;
    const int n0   = blockIdx.x * BN;
    const int jb   = blockIdx.x * 32;

    const uint32_t sbase = cvta_s(smraw);
    const uint32_t FULLB = sbase + 512;
    const uint32_t EMPTB = sbase + 512 + 24;

    if (tid == 0) {
        #pragma unroll
        for (int s = 0; s < NSTAGE; ++s) {
            mbar_init(FULLB + s * 8, 128);
            mbar_init(EMPTB + s * 8, 128);
        }
    }
    {   int g = tid >> 5, jj = tid & 31;
        int colg = g * 512 + jb + jj;
        biasS[tid] = bx[colg] + bh[colg];
    }
    __syncthreads();    // only CTA-wide barrier

    float acc[4][8][4];
    #pragma unroll
    for (int a = 0; a < 4; ++a)
        #pragma unroll
        for (int b = 0; b < 8; ++b)
            #pragma unroll
            for (int d = 0; d < 4; ++d) acc[a][b][d] = 0.0f;

    const int grp = lane >> 3, gi = lane & 7;
    const int a_row  = wm * 64 + (grp & 1) * 8 + gi;
    const int a_kofs = (grp >> 1) * 8;
    const uint32_t a_base = (uint32_t)(a_row * ROWSTR + a_kofs) * 2;
    const int b_row  = wn * 64 + (grp >> 1) * 8 + gi;
    const int b_kofs = (grp & 1) * 8;
    const uint32_t b_base = (uint32_t)(b_row * ROWSTR + b_kofs) * 2;

    auto load_stage = [&](int s, int kc) {
        const int k0 = kc * BK;
        char* As = stg0 + s * STG_B;
        char* Bs = As + A_STG_B;
        const __half* Ap = g_A16 + (size_t)m0 * Ktot + k0;
        #pragma unroll
        for (int p = 0; p < 8; ++p) {
            int q = tid + 128 * p, row = q >> 3, c8 = (q & 7) * 8;
            cpa16(cvta_s(As + (row * ROWSTR + c8) * 2),
                  Ap + (size_t)row * Ktot + c8);
        }
        const __half* Bp = g_Bt16 + (size_t)n0 * Ktot + k0;
        #pragma unroll
        for (int p = 0; p < 8; ++p) {
            int q = tid + 128 * p, row = q >> 3, c8 = (q & 7) * 8;
            cpa16(cvta_s(Bs + (row * ROWSTR + c8) * 2),
                  Bp + (size_t)row * Ktot + c8);
        }
        cpa_mbar_arrive(FULLB + s * 8);
    };

    load_stage(0, 0);
    load_stage(1, 1);

    uint32_t afr[2][4][4], bfr[2][4][4];
    int fph0 = 0, fph1 = 0, fph2 = 0;
    int eph0 = 0, eph1 = 0, eph2 = 0;

    // prologue: wait stage 0, preload its ks=0 fragments
    mbar_wait(FULLB + 0, 0); fph0 = 1;
    {
        const uint32_t sA = cvta_s(stg0);
        const uint32_t sB = sA + A_STG_B;
        #pragma unroll
        for (int mf = 0; mf < 4; ++mf)
            ldm4(afr[0][mf], sA + a_base + mf * (16 * ROWSTR * 2));
        #pragma unroll
        for (int np = 0; np < 4; ++np)
            ldm4(bfr[0][np], sB + b_base + np * (16 * ROWSTR * 2));
    }

    for (int it = 0; it < NITER; ++it) {
        const int s = it % NSTAGE;

        // producer: refill stage (it+2)%3 once its consumers drained
        if (it + 2 < NITER) {
            const int s2 = (it + 2) % NSTAGE;
            if (it > 0) {
                int ph = (s2 == 0) ? eph0 : (s2 == 1) ? eph1 : eph2;
                mbar_wait(EMPTB + s2 * 8, ph);
                if (s2 == 0) eph0 ^= 1; else if (s2 == 1) eph1 ^= 1; else eph2 ^= 1;
            }
            load_stage(s2, it + 2);
        }

        const uint32_t sA = cvta_s(stg0 + s * STG_B);
        const uint32_t sB = sA + A_STG_B;

        #pragma unroll
        for (int ks = 0; ks < 4; ++ks) {
            const int cur = ks & 1;       // stage starts even (4 steps/stage)
            const int nxt = cur ^ 1;
            if (ks < 3) {
                // prefetch this stage's next k16 fragments
                #pragma unroll
                for (int mf = 0; mf < 4; ++mf)
                    ldm4(afr[nxt][mf],
                         sA + a_base + mf * (16 * ROWSTR * 2) + (ks + 1) * 32);
                #pragma unroll
                for (int np = 0; np < 4; ++np)
                    ldm4(bfr[nxt][np],
                         sB + b_base + np * (16 * ROWSTR * 2) + (ks + 1) * 32);
                if (ks == 2)              // last smem read of stage s issued
                    mbar_arrive(EMPTB + s * 8);
            } else if (it + 1 < NITER) {
                // cross-stage prefetch: stage s+1, ks=0 (full normally posted)
                const int s1 = (it + 1) % NSTAGE;
                int ph = (s1 == 0) ? fph0 : (s1 == 1) ? fph1 : fph2;
                mbar_wait(FULLB + s1 * 8, ph);
                if (s1 == 0) fph0 ^= 1; else if (s1 == 1) fph1 ^= 1; else fph2 ^= 1;
                const uint32_t nA = cvta_s(stg0 + s1 * STG_B);
                const uint32_t nB = nA + A_STG_B;
                #pragma unroll
                for (int mf = 0; mf < 4; ++mf)
                    ldm4(afr[nxt][mf], nA + a_base + mf * (16 * ROWSTR * 2));
                #pragma unroll
                for (int np = 0; np < 4; ++np)
                    ldm4(bfr[nxt][np], nB + b_base + np * (16 * ROWSTR * 2));
            }
            #pragma unroll
            for (int mf = 0; mf < 4; ++mf)
                #pragma unroll
                for (int np = 0; np < 4; ++np) {
                    mma16(acc[mf][np * 2 + 0], afr[cur][mf], &bfr[cur][np][0]);
                    mma16(acc[mf][np * 2 + 1], afr[cur][mf], &bfr[cur][np][2]);
                }
        }
    }

    // ---- fused LSTM epilogue (thread-local: all 4 gates per j) ----
    const size_t HC = (size_t)Bsz * Hd;
    #pragma unroll
    for (int mf = 0; mf < 4; ++mf) {
        #pragma unroll
        for (int e = 0; e < 2; ++e) {
            size_t row = (size_t)m0 + wm * 64 + mf * 16 + (lane >> 2) + e * 8;
            #pragma unroll
            for (int half = 0; half < 2; ++half) {
                int q  = 2 * (lane & 3) + half * 8;
                int bq = wn * 16 + q;
                int j  = jb + bq;
                float2 cold = *reinterpret_cast<const float2*>(c + row * 512 + j);
                float hv[2], cv[2];
                #pragma unroll
                for (int d = 0; d < 2; ++d) {
                    float gi = acc[mf][0 + half][e * 2 + d] + biasS[     bq + d];
                    float gf = acc[mf][2 + half][e * 2 + d] + biasS[32 + bq + d];
                    float gg = acc[mf][4 + half][e * 2 + d] + biasS[64 + bq + d];
                    float go = acc[mf][6 + half][e * 2 + d] + biasS[96 + bq + d];
                    float i_ = sigm_(gi), f_ = sigm_(gf);
                    float g_ = tanh_(gg), o_ = sigm_(go);
                    float co = d ? cold.y : cold.x;
                    float cn = f_ * co + i_ * g_;
                    cv[d] = cn;
                    hv[d] = o_ * tanh_(cn);
                }
                *reinterpret_cast<float2*>(out + row * 512 + j) =
                    make_float2(hv[0], hv[1]);
                *reinterpret_cast<float2*>(out + HC + row * 512 + j) =
                    make_float2(cv[0], cv[1]);
            }
        }
    }
}

extern "C" void kernel_launch(void* const* d_in, const int* in_sizes, int n_in,
                              void* d_out, int out_size) {
    const float* x  = (const float*)d_in[0];
    const float* h  = (const float*)d_in[1];
    const float* c  = (const float*)d_in[2];
    const float* Wx = (const float*)d_in[3];
    const float* Wh = (const float*)d_in[4];
    const float* bx = (const float*)d_in[5];
    const float* bh = (const float*)d_in[6];
    float* out = (float*)d_out;

    static bool attr_set = false;
    if (!attr_set) {
        cudaFuncSetAttribute(lstm_mma,
                             cudaFuncAttributeMaxDynamicSharedMemorySize,
                             SMEM_BYTES);
        attr_set = true;
    }

    prep_all<<<PREP_BLKS, 256>>>(x, h, Wx, Wh);
    lstm_mma<<<dim3(FH / BN, Bsz / BM), 128, SMEM_BYTES>>>(c, bx, bh, out);
}